// round 8
// baseline (speedup 1.0000x reference)
#include <cuda_runtime.h>
#include <cuda_bf16.h>
#include <cstdint>

#define N_MAX 100352
#define E_MAX 1000000
#define HID 64

// ---------------- device scratch ----------------
__device__ float g_H [100000 * HID];          // h / residual (fp32)
__device__ float g_HW[100000 * HID];          // h @ w (fp32)
__device__ uint4 g_Hs[100000 * 16];           // h split hi/lo bf16, MMA-frag layout
__device__ float g_dinv[N_MAX];
__device__ int   g_hist[N_MAX];
__device__ int   g_offs[N_MAX];
__device__ int   g_cur [N_MAX];
__device__ unsigned long long g_state[256];
__device__ int   g_esrc[E_MAX];
__device__ int   g_is64;

// ---------------- edge access ----------------
__device__ __forceinline__ int edge_at(const void* ei, int idx) {
    if (g_is64) return (int)((const long long*)ei)[idx];
    return ((const int*)ei)[idx];
}

// ---------------- zero hist + scan state + dtype detect ----------------
__global__ void k_zero_detect(const unsigned long long* __restrict__ ei, int n) {
    int i = blockIdx.x * blockDim.x + threadIdx.x;
    if (i < n) g_hist[i] = 0;
    if (i < 256) g_state[i] = 0ull;
    if (blockIdx.x == 0) {
        int local = 0;
        for (int j = threadIdx.x; j < 1024; j += blockDim.x)
            if ((ei[j] >> 32) != 0ull) local = 1;
        int any = __syncthreads_or(local);
        if (threadIdx.x == 0) g_is64 = (any == 0);
    }
}

__global__ void k_hist(const void* __restrict__ ei, int E) {
    int e = blockIdx.x * blockDim.x + threadIdx.x;
    if (e < E) atomicAdd(&g_hist[edge_at(ei, E + e)], 1);
}

// ---------------- single-pass scan (decoupled lookback) + dinv ----------
__global__ __launch_bounds__(512) void k_scan_lb(int n) {
    int blk = blockIdx.x;
    int idx = blk * 512 + threadIdx.x;
    int v = (idx < n) ? g_hist[idx] : 0;
    if (idx < n) g_dinv[idx] = rsqrtf((float)v + 1.0f);

    int lane = threadIdx.x & 31, wid = threadIdx.x >> 5;
    int inc = v;
    #pragma unroll
    for (int o = 1; o < 32; o <<= 1) {
        int t = __shfl_up_sync(0xffffffffu, inc, o);
        if (lane >= o) inc += t;
    }
    __shared__ int wsum[16];
    if (lane == 31) wsum[wid] = inc;
    __syncthreads();
    if (wid == 0) {
        int s = (lane < 16) ? wsum[lane] : 0;
        #pragma unroll
        for (int o = 1; o < 16; o <<= 1) {
            int t = __shfl_up_sync(0xffffffffu, s, o);
            if (lane >= o) s += t;
        }
        if (lane < 16) wsum[lane] = s;
    }
    __syncthreads();
    int base_local = (wid > 0) ? wsum[wid - 1] : 0;
    int total = wsum[15];

    __shared__ unsigned long long s_prefix;
    if (threadIdx.x == 0) {
        if (blk == 0) {
            atomicExch(&g_state[0], (2ULL << 32) | (unsigned)total);
            s_prefix = 0ull;
        } else {
            atomicExch(&g_state[blk], (1ULL << 32) | (unsigned)total);
            unsigned long long run = 0;
            int j = blk - 1;
            while (true) {
                unsigned long long s = atomicAdd(&g_state[j], 0ULL);
                unsigned st = (unsigned)(s >> 32);
                if (st == 0) { __nanosleep(40); continue; }
                run += (unsigned)s;
                if (st == 2u) break;
                j--;
            }
            atomicExch(&g_state[blk], (2ULL << 32) | (unsigned)(run + total));
            s_prefix = run;
        }
    }
    __syncthreads();
    int excl = (int)(unsigned)s_prefix + base_local + inc - v;
    if (idx < n) { g_offs[idx] = excl; g_cur[idx] = excl; }
}

__global__ void k_place(const void* __restrict__ ei, int E) {
    int e = blockIdx.x * blockDim.x + threadIdx.x;
    if (e < E) {
        int s = edge_at(ei, e);
        int d = edge_at(ei, E + e);
        int pos = atomicAdd(&g_cur[d], 1);
        g_esrc[pos] = s;
    }
}

// ---------------- split helpers ----------------
__device__ __forceinline__ unsigned packsplit(float x, float y, unsigned& lo) {
    __nv_bfloat162 h = __float22bfloat162_rn(make_float2(x, y));
    float hx = __bfloat162float(h.x), hy = __bfloat162float(h.y);
    __nv_bfloat162 l = __float22bfloat162_rn(make_float2(x - hx, y - hy));
    lo = *(unsigned*)&l;
    return *(unsigned*)&h;
}

__device__ __forceinline__ void mma16816(float* c, const unsigned* a,
                                         unsigned b0, unsigned b1) {
    asm volatile(
        "mma.sync.aligned.m16n8k16.row.col.f32.bf16.bf16.f32 "
        "{%0,%1,%2,%3}, {%4,%5,%6,%7}, {%8,%9}, {%0,%1,%2,%3};"
        : "+f"(c[0]), "+f"(c[1]), "+f"(c[2]), "+f"(c[3])
        : "r"(a[0]), "r"(a[1]), "r"(a[2]), "r"(a[3]), "r"(b0), "r"(b1));
}

// W smem frag layout: uint4 {hi_lowk, hi_highk, lo_lowk, lo_highk}
// index [n][kc][q] flat = n*20 + kc*4 + q (pad 20 -> conflict-free phases)
#define WPAD 20

// fill one 64-k half of W into packed smem
__device__ __forceinline__ void fill_wf(uint4* Wf, const float* __restrict__ W,
                                        int kh, int tid) {
    for (int i = tid; i < 1024; i += 256) {
        int nn = i >> 4;
        int kc = (i >> 2) & 3;
        int q  = i & 3;
        int kb = kh * 64 + kc * 16 + q * 2;
        float w00 = W[(kb + 0) * 64 + nn], w01 = W[(kb + 1) * 64 + nn];
        float w10 = W[(kb + 8) * 64 + nn], w11 = W[(kb + 9) * 64 + nn];
        unsigned lo0, lo1;
        unsigned hi0 = packsplit(w00, w01, lo0);
        unsigned hi1 = packsplit(w10, w11, lo1);
        Wf[nn * WPAD + kc * 4 + q] = make_uint4(hi0, hi1, lo0, lo1);
    }
}

// ---------------- proj GEMM: H = x @ proj_w + b, K=128 ------------------
// also writes g_Hs (split bf16, frag layout)
__global__ __launch_bounds__(256) void k_proj(
    const float* __restrict__ A, const float* __restrict__ W,
    const float* __restrict__ bias, int n)
{
    __shared__ uint4 Wf[2][64 * WPAD];   // 40 KB
    int tid = threadIdx.x;
    fill_wf(Wf[0], W, 0, tid);
    fill_wf(Wf[1], W, 1, tid);
    __syncthreads();

    int warp = tid >> 5, lane = tid & 31;
    int r = lane >> 2, q = lane & 3;
    int row0 = blockIdx.x * 128 + warp * 16 + r;
    int rowA0 = min(row0, n - 1);
    int rowA1 = min(row0 + 8, n - 1);
    const float* base0 = A + (size_t)rowA0 * 128;
    const float* base1 = A + (size_t)rowA1 * 128;

    float c[8][4];
    #pragma unroll
    for (int nf = 0; nf < 8; nf++)
        #pragma unroll
        for (int j = 0; j < 4; j++) c[nf][j] = 0.0f;

    #pragma unroll
    for (int kh = 0; kh < 2; kh++) {
        const uint4* wf = Wf[kh];
        #pragma unroll
        for (int kc2 = 0; kc2 < 2; kc2++) {          // 2 kc per chunk
            float2 v[2][4];
            #pragma unroll
            for (int u = 0; u < 2; u++) {
                int kbase = kh * 64 + (kc2 * 2 + u) * 16 + q * 2;
                v[u][0] = *(const float2*)(base0 + kbase);
                v[u][1] = *(const float2*)(base1 + kbase);
                v[u][2] = *(const float2*)(base0 + kbase + 8);
                v[u][3] = *(const float2*)(base1 + kbase + 8);
            }
            #pragma unroll
            for (int u = 0; u < 2; u++) {
                int kc = kc2 * 2 + u;
                unsigned ah[4], al[4];
                #pragma unroll
                for (int j = 0; j < 4; j++)
                    ah[j] = packsplit(v[u][j].x, v[u][j].y, al[j]);
                #pragma unroll
                for (int nf = 0; nf < 8; nf++) {
                    uint4 b = wf[(nf * 8 + r) * WPAD + kc * 4 + q];
                    mma16816(c[nf], ah, b.x, b.y);
                    mma16816(c[nf], al, b.x, b.y);
                    mma16816(c[nf], ah, b.z, b.w);
                }
            }
        }
    }

    // epilogue: bias, write g_H fp32 + g_Hs split
    #pragma unroll
    for (int nf = 0; nf < 8; nf++) {
        float2 bb = *(const float2*)(bias + nf * 8 + q * 2);
        c[nf][0] += bb.x; c[nf][1] += bb.y;
        c[nf][2] += bb.x; c[nf][3] += bb.y;
    }
    #pragma unroll
    for (int nf = 0; nf < 8; nf++) {
        int col = nf * 8 + q * 2;
        if (row0 < n)
            *(float2*)(g_H + (size_t)row0 * 64 + col) = make_float2(c[nf][0], c[nf][1]);
        if (row0 + 8 < n)
            *(float2*)(g_H + (size_t)(row0 + 8) * 64 + col) = make_float2(c[nf][2], c[nf][3]);
    }
    #pragma unroll
    for (int kcp = 0; kcp < 4; kcp++) {
        int nfA = 2 * kcp, nfB = 2 * kcp + 1;
        unsigned lo0, lo1;
        if (row0 < n) {
            unsigned hi0 = packsplit(c[nfA][0], c[nfA][1], lo0);
            unsigned hi1 = packsplit(c[nfB][0], c[nfB][1], lo1);
            g_Hs[(size_t)row0 * 16 + kcp * 4 + q] = make_uint4(hi0, hi1, lo0, lo1);
        }
        if (row0 + 8 < n) {
            unsigned hi0 = packsplit(c[nfA][2], c[nfA][3], lo0);
            unsigned hi1 = packsplit(c[nfB][2], c[nfB][3], lo1);
            g_Hs[(size_t)(row0 + 8) * 16 + kcp * 4 + q] = make_uint4(hi0, hi1, lo0, lo1);
        }
    }
}

// ---------------- layer GEMM: HW = H @ w, K=64, A pre-split -------------
__global__ __launch_bounds__(256) void k_layer(const float* __restrict__ W, int n)
{
    __shared__ uint4 Wf[64 * WPAD];   // 20 KB
    int tid = threadIdx.x;
    fill_wf(Wf, W, 0, tid);
    __syncthreads();

    int warp = tid >> 5, lane = tid & 31;
    int r = lane >> 2, q = lane & 3;
    int row0 = blockIdx.x * 128 + warp * 16 + r;
    int rowA0 = min(row0, n - 1);
    int rowA1 = min(row0 + 8, n - 1);

    // prefetch all A frags for the k-range (4 kc x 2 rows)
    uint4 a0[4], a1[4];
    #pragma unroll
    for (int kc = 0; kc < 4; kc++) {
        a0[kc] = g_Hs[(size_t)rowA0 * 16 + kc * 4 + q];
        a1[kc] = g_Hs[(size_t)rowA1 * 16 + kc * 4 + q];
    }

    float c[8][4];
    #pragma unroll
    for (int nf = 0; nf < 8; nf++)
        #pragma unroll
        for (int j = 0; j < 4; j++) c[nf][j] = 0.0f;

    #pragma unroll
    for (int kc = 0; kc < 4; kc++) {
        unsigned ah[4] = { a0[kc].x, a1[kc].x, a0[kc].y, a1[kc].y };
        unsigned al[4] = { a0[kc].z, a1[kc].z, a0[kc].w, a1[kc].w };
        #pragma unroll
        for (int nf = 0; nf < 8; nf++) {
            uint4 b = Wf[(nf * 8 + r) * WPAD + kc * 4 + q];
            mma16816(c[nf], ah, b.x, b.y);
            mma16816(c[nf], al, b.x, b.y);
            mma16816(c[nf], ah, b.z, b.w);
        }
    }

    #pragma unroll
    for (int nf = 0; nf < 8; nf++) {
        int col = nf * 8 + q * 2;
        if (row0 < n)
            *(float2*)(g_HW + (size_t)row0 * 64 + col) = make_float2(c[nf][0], c[nf][1]);
        if (row0 + 8 < n)
            *(float2*)(g_HW + (size_t)(row0 + 8) * 64 + col) = make_float2(c[nf][2], c[nf][3]);
    }
}

// ---------------- fused aggregate + bias + LN (+ReLU+residual) ----------
__global__ void k_agg(const float* __restrict__ bias, const float* __restrict__ gma,
                      const float* __restrict__ beta, float* __restrict__ out_ext,
                      int n, int relu_res)
{
    int node = (blockIdx.x * blockDim.x + threadIdx.x) >> 5;
    if (node >= n) return;
    int lane = threadIdx.x & 31;
    float* out = out_ext ? out_ext : (float*)g_H;

    float di = g_dinv[node];
    float2 a0 = ((const float2*)(g_HW + (size_t)node * HID))[lane];
    a0.x *= di; a0.y *= di;
    float2 a1 = make_float2(0.f, 0.f), a2 = a1, a3 = a1;

    int e = g_offs[node];
    int e_end = e + g_hist[node];
    for (; e + 4 <= e_end; e += 4) {
        int s0 = g_esrc[e],     s1 = g_esrc[e + 1];
        int s2 = g_esrc[e + 2], s3 = g_esrc[e + 3];
        float n0 = g_dinv[s0], n1 = g_dinv[s1], n2 = g_dinv[s2], n3 = g_dinv[s3];
        float2 v0 = ((const float2*)(g_HW + (size_t)s0 * HID))[lane];
        float2 v1 = ((const float2*)(g_HW + (size_t)s1 * HID))[lane];
        float2 v2 = ((const float2*)(g_HW + (size_t)s2 * HID))[lane];
        float2 v3 = ((const float2*)(g_HW + (size_t)s3 * HID))[lane];
        a0.x = fmaf(v0.x, n0, a0.x); a0.y = fmaf(v0.y, n0, a0.y);
        a1.x = fmaf(v1.x, n1, a1.x); a1.y = fmaf(v1.y, n1, a1.y);
        a2.x = fmaf(v2.x, n2, a2.x); a2.y = fmaf(v2.y, n2, a2.y);
        a3.x = fmaf(v3.x, n3, a3.x); a3.y = fmaf(v3.y, n3, a3.y);
    }
    for (; e < e_end; e++) {
        int s0 = g_esrc[e];
        float n0 = g_dinv[s0];
        float2 v0 = ((const float2*)(g_HW + (size_t)s0 * HID))[lane];
        a0.x = fmaf(v0.x, n0, a0.x); a0.y = fmaf(v0.y, n0, a0.y);
    }
    float2 acc = make_float2((a0.x + a1.x) + (a2.x + a3.x),
                             (a0.y + a1.y) + (a2.y + a3.y));
    acc.x *= di; acc.y *= di;

    float2 bb = ((const float2*)bias)[lane];
    acc.x += bb.x; acc.y += bb.y;

    float sum = acc.x + acc.y;
    #pragma unroll
    for (int o = 16; o; o >>= 1) sum += __shfl_xor_sync(0xffffffffu, sum, o);
    float mu = sum * (1.0f / 64.0f);
    float dx = acc.x - mu, dy = acc.y - mu;
    float vs = dx * dx + dy * dy;
    #pragma unroll
    for (int o = 16; o; o >>= 1) vs += __shfl_xor_sync(0xffffffffu, vs, o);
    float rstd = rsqrtf(vs * (1.0f / 64.0f) + 1e-5f);
    float2 gg = ((const float2*)gma)[lane];
    float2 be = ((const float2*)beta)[lane];
    float ox = dx * rstd * gg.x + be.x;
    float oy = dy * rstd * gg.y + be.y;

    if (relu_res) {
        float2 rr = ((const float2*)(g_H + (size_t)node * HID))[lane];
        ox = fmaxf(ox, 0.0f) + rr.x;
        oy = fmaxf(oy, 0.0f) + rr.y;
        // write fp32 H (residual) and split Hs for next layer GEMM
        ((float2*)(g_H + (size_t)node * HID))[lane] = make_float2(ox, oy);
        unsigned lo;
        unsigned hi = packsplit(ox, oy, lo);
        unsigned hi_p = __shfl_down_sync(0xffffffffu, hi, 4);
        unsigned lo_p = __shfl_down_sync(0xffffffffu, lo, 4);
        if ((lane & 4) == 0) {
            int kc = lane >> 3, qq = lane & 3;
            g_Hs[(size_t)node * 16 + kc * 4 + qq] = make_uint4(hi, hi_p, lo, lo_p);
        }
    } else {
        ((float2*)(out + (size_t)node * HID))[lane] = make_float2(ox, oy);
    }
}

// ---------------- launch ----------------
extern "C" void kernel_launch(void* const* d_in, const int* in_sizes, int n_in,
                              void* d_out, int out_size)
{
    const float* x      = (const float*)d_in[0];
    const void*  ei     = d_in[1];
    const float* proj_w = (const float*)d_in[2];
    const float* proj_b = (const float*)d_in[3];
    const float* w[3]  = { (const float*)d_in[4],  (const float*)d_in[8],  (const float*)d_in[12] };
    const float* b[3]  = { (const float*)d_in[5],  (const float*)d_in[9],  (const float*)d_in[13] };
    const float* gm[3] = { (const float*)d_in[6],  (const float*)d_in[10], (const float*)d_in[14] };
    const float* bt[3] = { (const float*)d_in[7],  (const float*)d_in[11], (const float*)d_in[15] };

    int n = in_sizes[0] / 128;    // 100000
    int E = in_sizes[1] / 2;      // 1000000
    float* out = (float*)d_out;

    int nb512 = (n + 511) / 512;
    int gemm_blocks = (n + 127) / 128;

    k_zero_detect<<<(n + 255) / 256, 256>>>((const unsigned long long*)ei, n);  // 0
    k_hist<<<(E + 255) / 256, 256>>>(ei, E);                                     // 1
    k_scan_lb<<<nb512, 512>>>(n);                                                // 2
    k_proj<<<gemm_blocks, 256>>>(x, proj_w, proj_b, n);                          // 3 <- profiled
    k_place<<<(E + 255) / 256, 256>>>(ei, E);                                    // 4

    int agg_blocks = (n + 7) / 8;
    for (int l = 0; l < 3; l++) {
        k_layer<<<gemm_blocks, 256>>>(w[l], n);
        float* dst = (l < 2) ? nullptr : out;
        k_agg<<<agg_blocks, 256>>>(b[l], gm[l], bt[l], dst, n, (l < 2) ? 1 : 0);
    }
}

// round 9
// speedup vs baseline: 1.0681x; 1.0681x over previous
#include <cuda_runtime.h>
#include <cuda_bf16.h>
#include <cuda_fp16.h>
#include <cstdint>

#define N_MAX 100352
#define E_MAX 1000000
#define HID 64

// ---------------- device scratch ----------------
__device__ float  g_H  [100000 * HID];   // h / residual (fp32)
__device__ __half g_HWh[100000 * HID];   // h @ w (fp16, agg-only consumer)
__device__ float g_dinv[N_MAX];
__device__ int   g_hist[N_MAX];
__device__ int   g_offs[N_MAX];
__device__ int   g_cur [N_MAX];
__device__ int   g_part[256];
__device__ int   g_esrc[E_MAX];
__device__ int   g_is64;

// ---------------- edge access ----------------
__device__ __forceinline__ int edge_at(const void* ei, int idx) {
    if (g_is64) return (int)((const long long*)ei)[idx];
    return ((const int*)ei)[idx];
}

// ---------------- zero hist + dtype detect (merged) ----------------
__global__ void k_zero_detect(const unsigned long long* __restrict__ ei, int n) {
    int i = blockIdx.x * blockDim.x + threadIdx.x;
    if (i < n) g_hist[i] = 0;
    if (blockIdx.x == 0) {
        int local = 0;
        for (int j = threadIdx.x; j < 1024; j += blockDim.x)
            if ((ei[j] >> 32) != 0ull) local = 1;
        int any = __syncthreads_or(local);
        if (threadIdx.x == 0) g_is64 = (any == 0);
    }
}

__global__ void k_hist(const void* __restrict__ ei, int E) {
    int e = blockIdx.x * blockDim.x + threadIdx.x;
    if (e < E) atomicAdd(&g_hist[edge_at(ei, E + e)], 1);
}

// ---------------- scan1 (+dinv merged) ----------------
__global__ void k_scan1(int n) {
    int idx = blockIdx.x * 512 + threadIdx.x;
    int v = (idx < n) ? g_hist[idx] : 0;
    if (idx < n) g_dinv[idx] = rsqrtf((float)v + 1.0f);
    int lane = threadIdx.x & 31, wid = threadIdx.x >> 5;
    int inc = v;
    #pragma unroll
    for (int o = 1; o < 32; o <<= 1) {
        int t = __shfl_up_sync(0xffffffffu, inc, o);
        if (lane >= o) inc += t;
    }
    __shared__ int wsum[16];
    if (lane == 31) wsum[wid] = inc;
    __syncthreads();
    if (wid == 0) {
        int s = (lane < 16) ? wsum[lane] : 0;
        #pragma unroll
        for (int o = 1; o < 16; o <<= 1) {
            int t = __shfl_up_sync(0xffffffffu, s, o);
            if (lane >= o) s += t;
        }
        if (lane < 16) wsum[lane] = s;
    }
    __syncthreads();
    int base = (wid > 0) ? wsum[wid - 1] : 0;
    if (idx < n) g_offs[idx] = base + inc - v;
    if (threadIdx.x == 0) g_part[blockIdx.x] = wsum[15];
}

__global__ void k_scan2(int nb) {
    int t = threadIdx.x;
    int v = (t < nb) ? g_part[t] : 0;
    int lane = t & 31, wid = t >> 5;
    int inc = v;
    #pragma unroll
    for (int o = 1; o < 32; o <<= 1) {
        int s = __shfl_up_sync(0xffffffffu, inc, o);
        if (lane >= o) inc += s;
    }
    __shared__ int wsum[8];
    if (lane == 31) wsum[wid] = inc;
    __syncthreads();
    if (wid == 0) {
        int s = (lane < 8) ? wsum[lane] : 0;
        #pragma unroll
        for (int o = 1; o < 8; o <<= 1) {
            int u = __shfl_up_sync(0xffffffffu, s, o);
            if (lane >= o) s += u;
        }
        if (lane < 8) wsum[lane] = s;
    }
    __syncthreads();
    int base = (wid > 0) ? wsum[wid - 1] : 0;
    if (t < nb) g_part[t] = base + inc - v;
}

__global__ void k_scan3(int n) {
    int idx = blockIdx.x * 512 + threadIdx.x;
    if (idx < n) {
        int o = g_offs[idx] + g_part[blockIdx.x];
        g_offs[idx] = o;
        g_cur[idx]  = o;
    }
}

__global__ void k_place(const void* __restrict__ ei, int E) {
    int e = blockIdx.x * blockDim.x + threadIdx.x;
    if (e < E) {
        int s = edge_at(ei, e);
        int d = edge_at(ei, E + e);
        int pos = atomicAdd(&g_cur[d], 1);
        g_esrc[pos] = s;
    }
}

// ---------------- bf16 split helpers ----------------
__device__ __forceinline__ unsigned short bits_of(__nv_bfloat16 h) {
    return *(unsigned short*)&h;
}
__device__ __forceinline__ void split2(float x, float y, unsigned& hi, unsigned& lo) {
    __nv_bfloat16 hx = __float2bfloat16_rn(x);
    __nv_bfloat16 hy = __float2bfloat16_rn(y);
    __nv_bfloat16 lx = __float2bfloat16_rn(x - __bfloat162float(hx));
    __nv_bfloat16 ly = __float2bfloat16_rn(y - __bfloat162float(hy));
    hi = (unsigned)bits_of(hx) | ((unsigned)bits_of(hy) << 16);
    lo = (unsigned)bits_of(lx) | ((unsigned)bits_of(ly) << 16);
}

__device__ __forceinline__ void mma16816(float* c, const unsigned* a,
                                         unsigned b0, unsigned b1) {
    asm volatile(
        "mma.sync.aligned.m16n8k16.row.col.f32.bf16.bf16.f32 "
        "{%0,%1,%2,%3}, {%4,%5,%6,%7}, {%8,%9}, {%0,%1,%2,%3};"
        : "+f"(c[0]), "+f"(c[1]), "+f"(c[2]), "+f"(c[3])
        : "r"(a[0]), "r"(a[1]), "r"(a[2]), "r"(a[3]), "r"(b0), "r"(b1));
}

// ---------------- tensor GEMM: C[n,64] = A[n,K] @ W[K,64] (+bias) --------
// dst=0 -> g_H (fp32), dst=1 -> g_HWh (fp16)
__global__ __launch_bounds__(256) void k_tgemm(
    const float* __restrict__ Aext, const float* __restrict__ W,
    const float* __restrict__ bias, int dst, int n, int K)
{
    const float* A = Aext ? Aext : (const float*)g_H;

    __shared__ __nv_bfloat16 Wh[64][72];
    __shared__ __nv_bfloat16 Wl[64][72];

    int tid = threadIdx.x;
    if (K == 64) {
        #pragma unroll
        for (int u = 0; u < 16; u++) {
            int i = tid * 16 + u;
            int kk = i >> 6, nn = i & 63;
            float wv = W[i];
            __nv_bfloat16 h = __float2bfloat16_rn(wv);
            __nv_bfloat16 l = __float2bfloat16_rn(wv - __bfloat162float(h));
            Wh[nn][kk] = h; Wl[nn][kk] = l;
        }
    }

    int row_base = blockIdx.x * 128;
    int warp = tid >> 5, lane = tid & 31;
    int r = lane >> 2, q = lane & 3;
    int row0 = row_base + warp * 16 + r;
    int rowA0 = min(row0, n - 1);
    int rowA1 = min(row0 + 8, n - 1);

    float c[8][4];
    #pragma unroll
    for (int nf = 0; nf < 8; nf++)
        #pragma unroll
        for (int j = 0; j < 4; j++) c[nf][j] = 0.0f;

    int khalves = K >> 6;
    for (int kh = 0; kh < khalves; kh++) {
        if (K == 128) {
            __syncthreads();
            for (int i = tid; i < 64 * 64; i += 256) {
                int kk = i >> 6, nn = i & 63;
                float wv = W[(kh * 64 + kk) * 64 + nn];
                __nv_bfloat16 h = __float2bfloat16_rn(wv);
                __nv_bfloat16 l = __float2bfloat16_rn(wv - __bfloat162float(h));
                Wh[nn][kk] = h; Wl[nn][kk] = l;
            }
        }
        __syncthreads();

        #pragma unroll
        for (int kc = 0; kc < 4; kc++) {
            int kbase = kh * 64 + kc * 16 + q * 2;
            const float* p0 = A + (size_t)rowA0 * K + kbase;
            const float* p1 = A + (size_t)rowA1 * K + kbase;
            float2 v0 = *(const float2*)p0;
            float2 v1 = *(const float2*)p1;
            float2 v2 = *(const float2*)(p0 + 8);
            float2 v3 = *(const float2*)(p1 + 8);
            unsigned ah[4], al[4];
            split2(v0.x, v0.y, ah[0], al[0]);
            split2(v1.x, v1.y, ah[1], al[1]);
            split2(v2.x, v2.y, ah[2], al[2]);
            split2(v3.x, v3.y, ah[3], al[3]);

            #pragma unroll
            for (int nf = 0; nf < 8; nf++) {
                int bn = nf * 8 + r;
                int bk = kc * 16 + q * 2;
                unsigned bh0 = *(const unsigned*)&Wh[bn][bk];
                unsigned bh1 = *(const unsigned*)&Wh[bn][bk + 8];
                unsigned bl0 = *(const unsigned*)&Wl[bn][bk];
                unsigned bl1 = *(const unsigned*)&Wl[bn][bk + 8];
                mma16816(c[nf], ah, bh0, bh1);
                mma16816(c[nf], al, bh0, bh1);
                mma16816(c[nf], ah, bl0, bl1);
            }
        }
    }

    if (dst == 0) {
        #pragma unroll
        for (int nf = 0; nf < 8; nf++) {
            int col = nf * 8 + q * 2;
            float bx = 0.f, by = 0.f;
            if (bias) { float2 bb = *(const float2*)(bias + col); bx = bb.x; by = bb.y; }
            if (row0 < n)
                *(float2*)(g_H + (size_t)row0 * 64 + col) =
                    make_float2(c[nf][0] + bx, c[nf][1] + by);
            if (row0 + 8 < n)
                *(float2*)(g_H + (size_t)(row0 + 8) * 64 + col) =
                    make_float2(c[nf][2] + bx, c[nf][3] + by);
        }
    } else {
        __half2* Cp = (__half2*)g_HWh;
        #pragma unroll
        for (int nf = 0; nf < 8; nf++) {
            int colh = nf * 4 + q;     // half2 index within row
            if (row0 < n)
                Cp[(size_t)row0 * 32 + colh] = __floats2half2_rn(c[nf][0], c[nf][1]);
            if (row0 + 8 < n)
                Cp[(size_t)(row0 + 8) * 32 + colh] = __floats2half2_rn(c[nf][2], c[nf][3]);
        }
    }
}

// ---------------- fused aggregate + bias + LN (+ReLU+residual) ----------
// one warp per node; gathers fp16 HW rows (half traffic), fp32 accumulate
__global__ void k_agg(const float* __restrict__ bias, const float* __restrict__ gma,
                      const float* __restrict__ beta, float* __restrict__ out_ext,
                      int n, int relu_res)
{
    int node = (blockIdx.x * blockDim.x + threadIdx.x) >> 5;
    if (node >= n) return;
    int lane = threadIdx.x & 31;
    float* out = out_ext ? out_ext : (float*)g_H;
    const __half2* HW = (const __half2*)g_HWh;

    float di = g_dinv[node];
    float2 acc = __half22float2(HW[(size_t)node * 32 + lane]);
    float self = di * di;
    acc.x *= self; acc.y *= self;
    float2 accB = make_float2(0.f, 0.f);

    int e = g_offs[node];
    int e_end = e + g_hist[node];
    for (; e + 2 <= e_end; e += 2) {
        int sa = g_esrc[e];
        int sb = g_esrc[e + 1];
        float na = g_dinv[sa] * di;
        float nb = g_dinv[sb] * di;
        float2 va = __half22float2(HW[(size_t)sa * 32 + lane]);
        float2 vb = __half22float2(HW[(size_t)sb * 32 + lane]);
        acc.x  = fmaf(va.x, na, acc.x);  acc.y  = fmaf(va.y, na, acc.y);
        accB.x = fmaf(vb.x, nb, accB.x); accB.y = fmaf(vb.y, nb, accB.y);
    }
    if (e < e_end) {
        int sa = g_esrc[e];
        float na = g_dinv[sa] * di;
        float2 va = __half22float2(HW[(size_t)sa * 32 + lane]);
        acc.x = fmaf(va.x, na, acc.x); acc.y = fmaf(va.y, na, acc.y);
    }
    acc.x += accB.x; acc.y += accB.y;

    float2 bb = ((const float2*)bias)[lane];
    acc.x += bb.x; acc.y += bb.y;

    float sum = acc.x + acc.y;
    #pragma unroll
    for (int o = 16; o; o >>= 1) sum += __shfl_xor_sync(0xffffffffu, sum, o);
    float mu = sum * (1.0f / 64.0f);
    float dx = acc.x - mu, dy = acc.y - mu;
    float vs = dx * dx + dy * dy;
    #pragma unroll
    for (int o = 16; o; o >>= 1) vs += __shfl_xor_sync(0xffffffffu, vs, o);
    float rstd = rsqrtf(vs * (1.0f / 64.0f) + 1e-5f);
    float2 gg = ((const float2*)gma)[lane];
    float2 be = ((const float2*)beta)[lane];
    float ox = dx * rstd * gg.x + be.x;
    float oy = dy * rstd * gg.y + be.y;

    if (relu_res) {
        float2 rr = ((const float2*)(g_H + (size_t)node * HID))[lane];
        ox = fmaxf(ox, 0.0f) + rr.x;
        oy = fmaxf(oy, 0.0f) + rr.y;
    }
    ((float2*)(out + (size_t)node * HID))[lane] = make_float2(ox, oy);
}

// ---------------- launch ----------------
extern "C" void kernel_launch(void* const* d_in, const int* in_sizes, int n_in,
                              void* d_out, int out_size)
{
    const float* x      = (const float*)d_in[0];
    const void*  ei     = d_in[1];
    const float* proj_w = (const float*)d_in[2];
    const float* proj_b = (const float*)d_in[3];
    const float* w[3]  = { (const float*)d_in[4],  (const float*)d_in[8],  (const float*)d_in[12] };
    const float* b[3]  = { (const float*)d_in[5],  (const float*)d_in[9],  (const float*)d_in[13] };
    const float* gm[3] = { (const float*)d_in[6],  (const float*)d_in[10], (const float*)d_in[14] };
    const float* bt[3] = { (const float*)d_in[7],  (const float*)d_in[11], (const float*)d_in[15] };

    int n = in_sizes[0] / 128;    // 100000
    int E = in_sizes[1] / 2;      // 1000000
    float* out = (float*)d_out;

    int nb512 = (n + 511) / 512;
    int gemm_blocks = (n + 127) / 128;

    k_zero_detect<<<(n + 255) / 256, 256>>>((const unsigned long long*)ei, n);    // 0
    k_hist<<<(E + 255) / 256, 256>>>(ei, E);                                       // 1
    k_scan1<<<nb512, 512>>>(n);                                                    // 2
    k_tgemm<<<gemm_blocks, 256>>>(x, proj_w, proj_b, /*dst=*/0, n, 128);           // 3 <- profiled
    k_scan2<<<1, 256>>>(nb512);                                                    // 4
    k_scan3<<<nb512, 512>>>(n);                                                    // 5
    k_place<<<(E + 255) / 256, 256>>>(ei, E);                                      // 6

    int agg_blocks = (n + 7) / 8;
    for (int l = 0; l < 3; l++) {
        k_tgemm<<<gemm_blocks, 256>>>(nullptr, w[l], nullptr, /*dst=*/1, n, 64);
        float* dst = (l < 2) ? nullptr : out;
        k_agg<<<agg_blocks, 256>>>(b[l], gm[l], bt[l], dst, n, (l < 2) ? 1 : 0);
    }
}

// round 10
// speedup vs baseline: 1.1568x; 1.0830x over previous
#include <cuda_runtime.h>
#include <cuda_bf16.h>
#include <cuda_fp16.h>
#include <cstdint>

#define N_MAX 100352
#define E_MAX 1000000
#define HID 64

// ---------------- device scratch ----------------
__device__ float  g_H  [100000 * HID];   // h / residual (fp32)
__device__ __half g_HWh[100000 * HID];   // dinv[row] * (h @ w)  (fp16, pre-scaled)
__device__ float g_dinv[N_MAX];
__device__ int   g_hist[N_MAX];
__device__ int   g_offs[N_MAX];
__device__ int   g_cur [N_MAX];
__device__ int   g_part[256];
__device__ int   g_esrc[E_MAX];
__device__ int   g_is64;

// ---------------- edge access ----------------
__device__ __forceinline__ int edge_at(const void* ei, int idx) {
    if (g_is64) return (int)((const long long*)ei)[idx];
    return ((const int*)ei)[idx];
}

// ---------------- zero hist + dtype detect (merged) ----------------
__global__ void k_zero_detect(const unsigned long long* __restrict__ ei, int n) {
    int i = blockIdx.x * blockDim.x + threadIdx.x;
    if (i < n) g_hist[i] = 0;
    if (blockIdx.x == 0) {
        int local = 0;
        for (int j = threadIdx.x; j < 1024; j += blockDim.x)
            if ((ei[j] >> 32) != 0ull) local = 1;
        int any = __syncthreads_or(local);
        if (threadIdx.x == 0) g_is64 = (any == 0);
    }
}

__global__ void k_hist(const void* __restrict__ ei, int E) {
    int e = blockIdx.x * blockDim.x + threadIdx.x;
    if (e < E) atomicAdd(&g_hist[edge_at(ei, E + e)], 1);
}

// ---------------- scan1 (+dinv merged) ----------------
__global__ void k_scan1(int n) {
    int idx = blockIdx.x * 512 + threadIdx.x;
    int v = (idx < n) ? g_hist[idx] : 0;
    if (idx < n) g_dinv[idx] = rsqrtf((float)v + 1.0f);
    int lane = threadIdx.x & 31, wid = threadIdx.x >> 5;
    int inc = v;
    #pragma unroll
    for (int o = 1; o < 32; o <<= 1) {
        int t = __shfl_up_sync(0xffffffffu, inc, o);
        if (lane >= o) inc += t;
    }
    __shared__ int wsum[16];
    if (lane == 31) wsum[wid] = inc;
    __syncthreads();
    if (wid == 0) {
        int s = (lane < 16) ? wsum[lane] : 0;
        #pragma unroll
        for (int o = 1; o < 16; o <<= 1) {
            int t = __shfl_up_sync(0xffffffffu, s, o);
            if (lane >= o) s += t;
        }
        if (lane < 16) wsum[lane] = s;
    }
    __syncthreads();
    int base = (wid > 0) ? wsum[wid - 1] : 0;
    if (idx < n) g_offs[idx] = base + inc - v;
    if (threadIdx.x == 0) g_part[blockIdx.x] = wsum[15];
}

__global__ void k_scan2(int nb) {
    int t = threadIdx.x;
    int v = (t < nb) ? g_part[t] : 0;
    int lane = t & 31, wid = t >> 5;
    int inc = v;
    #pragma unroll
    for (int o = 1; o < 32; o <<= 1) {
        int s = __shfl_up_sync(0xffffffffu, inc, o);
        if (lane >= o) inc += s;
    }
    __shared__ int wsum[8];
    if (lane == 31) wsum[wid] = inc;
    __syncthreads();
    if (wid == 0) {
        int s = (lane < 8) ? wsum[lane] : 0;
        #pragma unroll
        for (int o = 1; o < 8; o <<= 1) {
            int u = __shfl_up_sync(0xffffffffu, s, o);
            if (lane >= o) s += u;
        }
        if (lane < 8) wsum[lane] = s;
    }
    __syncthreads();
    int base = (wid > 0) ? wsum[wid - 1] : 0;
    if (t < nb) g_part[t] = base + inc - v;
}

__global__ void k_scan3(int n) {
    int idx = blockIdx.x * 512 + threadIdx.x;
    if (idx < n) {
        int o = g_offs[idx] + g_part[blockIdx.x];
        g_offs[idx] = o;
        g_cur[idx]  = o;
    }
}

__global__ void k_place(const void* __restrict__ ei, int E) {
    int e = blockIdx.x * blockDim.x + threadIdx.x;
    if (e < E) {
        int s = edge_at(ei, e);
        int d = edge_at(ei, E + e);
        int pos = atomicAdd(&g_cur[d], 1);
        g_esrc[pos] = s;
    }
}

// ---------------- bf16 split helpers ----------------
__device__ __forceinline__ unsigned short bits_of(__nv_bfloat16 h) {
    return *(unsigned short*)&h;
}
__device__ __forceinline__ void split2(float x, float y, unsigned& hi, unsigned& lo) {
    __nv_bfloat16 hx = __float2bfloat16_rn(x);
    __nv_bfloat16 hy = __float2bfloat16_rn(y);
    __nv_bfloat16 lx = __float2bfloat16_rn(x - __bfloat162float(hx));
    __nv_bfloat16 ly = __float2bfloat16_rn(y - __bfloat162float(hy));
    hi = (unsigned)bits_of(hx) | ((unsigned)bits_of(hy) << 16);
    lo = (unsigned)bits_of(lx) | ((unsigned)bits_of(ly) << 16);
}

__device__ __forceinline__ void mma16816(float* c, const unsigned* a,
                                         unsigned b0, unsigned b1) {
    asm volatile(
        "mma.sync.aligned.m16n8k16.row.col.f32.bf16.bf16.f32 "
        "{%0,%1,%2,%3}, {%4,%5,%6,%7}, {%8,%9}, {%0,%1,%2,%3};"
        : "+f"(c[0]), "+f"(c[1]), "+f"(c[2]), "+f"(c[3])
        : "r"(a[0]), "r"(a[1]), "r"(a[2]), "r"(a[3]), "r"(b0), "r"(b1));
}

// ---------------- tensor GEMM: C[n,64] = A[n,K] @ W[K,64] (+bias) --------
// dst=0 -> g_H (fp32, +bias), dst=1 -> g_HWh (fp16, pre-scaled by dinv[row])
__global__ __launch_bounds__(256) void k_tgemm(
    const float* __restrict__ Aext, const float* __restrict__ W,
    const float* __restrict__ bias, int dst, int n, int K)
{
    const float* A = Aext ? Aext : (const float*)g_H;

    __shared__ __nv_bfloat16 Wh[64][72];
    __shared__ __nv_bfloat16 Wl[64][72];

    int tid = threadIdx.x;
    if (K == 64) {
        #pragma unroll
        for (int u = 0; u < 16; u++) {
            int i = tid * 16 + u;
            int kk = i >> 6, nn = i & 63;
            float wv = W[i];
            __nv_bfloat16 h = __float2bfloat16_rn(wv);
            __nv_bfloat16 l = __float2bfloat16_rn(wv - __bfloat162float(h));
            Wh[nn][kk] = h; Wl[nn][kk] = l;
        }
    }

    int row_base = blockIdx.x * 128;
    int warp = tid >> 5, lane = tid & 31;
    int r = lane >> 2, q = lane & 3;
    int row0 = row_base + warp * 16 + r;
    int rowA0 = min(row0, n - 1);
    int rowA1 = min(row0 + 8, n - 1);

    float c[8][4];
    #pragma unroll
    for (int nf = 0; nf < 8; nf++)
        #pragma unroll
        for (int j = 0; j < 4; j++) c[nf][j] = 0.0f;

    int khalves = K >> 6;
    for (int kh = 0; kh < khalves; kh++) {
        if (K == 128) {
            __syncthreads();
            for (int i = tid; i < 64 * 64; i += 256) {
                int kk = i >> 6, nn = i & 63;
                float wv = W[(kh * 64 + kk) * 64 + nn];
                __nv_bfloat16 h = __float2bfloat16_rn(wv);
                __nv_bfloat16 l = __float2bfloat16_rn(wv - __bfloat162float(h));
                Wh[nn][kk] = h; Wl[nn][kk] = l;
            }
        }
        __syncthreads();

        #pragma unroll
        for (int kc = 0; kc < 4; kc++) {
            int kbase = kh * 64 + kc * 16 + q * 2;
            const float* p0 = A + (size_t)rowA0 * K + kbase;
            const float* p1 = A + (size_t)rowA1 * K + kbase;
            float2 v0 = *(const float2*)p0;
            float2 v1 = *(const float2*)p1;
            float2 v2 = *(const float2*)(p0 + 8);
            float2 v3 = *(const float2*)(p1 + 8);
            unsigned ah[4], al[4];
            split2(v0.x, v0.y, ah[0], al[0]);
            split2(v1.x, v1.y, ah[1], al[1]);
            split2(v2.x, v2.y, ah[2], al[2]);
            split2(v3.x, v3.y, ah[3], al[3]);

            #pragma unroll
            for (int nf = 0; nf < 8; nf++) {
                int bn = nf * 8 + r;
                int bk = kc * 16 + q * 2;
                unsigned bh0 = *(const unsigned*)&Wh[bn][bk];
                unsigned bh1 = *(const unsigned*)&Wh[bn][bk + 8];
                unsigned bl0 = *(const unsigned*)&Wl[bn][bk];
                unsigned bl1 = *(const unsigned*)&Wl[bn][bk + 8];
                mma16816(c[nf], ah, bh0, bh1);
                mma16816(c[nf], al, bh0, bh1);
                mma16816(c[nf], ah, bl0, bl1);
            }
        }
    }

    if (dst == 0) {
        #pragma unroll
        for (int nf = 0; nf < 8; nf++) {
            int col = nf * 8 + q * 2;
            float bx = 0.f, by = 0.f;
            if (bias) { float2 bb = *(const float2*)(bias + col); bx = bb.x; by = bb.y; }
            if (row0 < n)
                *(float2*)(g_H + (size_t)row0 * 64 + col) =
                    make_float2(c[nf][0] + bx, c[nf][1] + by);
            if (row0 + 8 < n)
                *(float2*)(g_H + (size_t)(row0 + 8) * 64 + col) =
                    make_float2(c[nf][2] + bx, c[nf][3] + by);
        }
    } else {
        __half2* Cp = (__half2*)g_HWh;
        float sc0 = (row0 < n) ? g_dinv[row0] : 0.f;
        float sc1 = (row0 + 8 < n) ? g_dinv[row0 + 8] : 0.f;
        #pragma unroll
        for (int nf = 0; nf < 8; nf++) {
            int colh = nf * 4 + q;
            if (row0 < n)
                Cp[(size_t)row0 * 32 + colh] =
                    __floats2half2_rn(c[nf][0] * sc0, c[nf][1] * sc0);
            if (row0 + 8 < n)
                Cp[(size_t)(row0 + 8) * 32 + colh] =
                    __floats2half2_rn(c[nf][2] * sc1, c[nf][3] * sc1);
        }
    }
}

// ---------------- fused aggregate + bias + LN (+ReLU+residual) ----------
// HW rows pre-scaled by dinv[src]: out = di*(HW'[node] + sum HW'[s]) + bias
// inner loop: 2 dependent loads (esrc -> row), pure adds, 4 chains
__global__ void k_agg(const float* __restrict__ bias, const float* __restrict__ gma,
                      const float* __restrict__ beta, float* __restrict__ out_ext,
                      int n, int relu_res)
{
    int node = (blockIdx.x * blockDim.x + threadIdx.x) >> 5;
    if (node >= n) return;
    int lane = threadIdx.x & 31;
    float* out = out_ext ? out_ext : (float*)g_H;
    const __half2* HW = (const __half2*)g_HWh;

    float di = g_dinv[node];
    float2 a0 = __half22float2(HW[(size_t)node * 32 + lane]);  // self term
    float2 a1 = make_float2(0.f, 0.f), a2 = a1, a3 = a1;

    int e = g_offs[node];
    int e_end = e + g_hist[node];
    for (; e + 4 <= e_end; e += 4) {
        int s0 = g_esrc[e],     s1 = g_esrc[e + 1];
        int s2 = g_esrc[e + 2], s3 = g_esrc[e + 3];
        float2 v0 = __half22float2(HW[(size_t)s0 * 32 + lane]);
        float2 v1 = __half22float2(HW[(size_t)s1 * 32 + lane]);
        float2 v2 = __half22float2(HW[(size_t)s2 * 32 + lane]);
        float2 v3 = __half22float2(HW[(size_t)s3 * 32 + lane]);
        a0.x += v0.x; a0.y += v0.y;
        a1.x += v1.x; a1.y += v1.y;
        a2.x += v2.x; a2.y += v2.y;
        a3.x += v3.x; a3.y += v3.y;
    }
    for (; e < e_end; e++) {
        int s0 = g_esrc[e];
        float2 v0 = __half22float2(HW[(size_t)s0 * 32 + lane]);
        a0.x += v0.x; a0.y += v0.y;
    }
    float2 acc = make_float2((a0.x + a1.x) + (a2.x + a3.x),
                             (a0.y + a1.y) + (a2.y + a3.y));
    acc.x *= di; acc.y *= di;

    float2 bb = ((const float2*)bias)[lane];
    acc.x += bb.x; acc.y += bb.y;

    float sum = acc.x + acc.y;
    #pragma unroll
    for (int o = 16; o; o >>= 1) sum += __shfl_xor_sync(0xffffffffu, sum, o);
    float mu = sum * (1.0f / 64.0f);
    float dx = acc.x - mu, dy = acc.y - mu;
    float vs = dx * dx + dy * dy;
    #pragma unroll
    for (int o = 16; o; o >>= 1) vs += __shfl_xor_sync(0xffffffffu, vs, o);
    float rstd = rsqrtf(vs * (1.0f / 64.0f) + 1e-5f);
    float2 gg = ((const float2*)gma)[lane];
    float2 be = ((const float2*)beta)[lane];
    float ox = dx * rstd * gg.x + be.x;
    float oy = dy * rstd * gg.y + be.y;

    if (relu_res) {
        float2 rr = ((const float2*)(g_H + (size_t)node * HID))[lane];
        ox = fmaxf(ox, 0.0f) + rr.x;
        oy = fmaxf(oy, 0.0f) + rr.y;
    }
    ((float2*)(out + (size_t)node * HID))[lane] = make_float2(ox, oy);
}

// ---------------- launch ----------------
extern "C" void kernel_launch(void* const* d_in, const int* in_sizes, int n_in,
                              void* d_out, int out_size)
{
    const float* x      = (const float*)d_in[0];
    const void*  ei     = d_in[1];
    const float* proj_w = (const float*)d_in[2];
    const float* proj_b = (const float*)d_in[3];
    const float* w[3]  = { (const float*)d_in[4],  (const float*)d_in[8],  (const float*)d_in[12] };
    const float* b[3]  = { (const float*)d_in[5],  (const float*)d_in[9],  (const float*)d_in[13] };
    const float* gm[3] = { (const float*)d_in[6],  (const float*)d_in[10], (const float*)d_in[14] };
    const float* bt[3] = { (const float*)d_in[7],  (const float*)d_in[11], (const float*)d_in[15] };

    int n = in_sizes[0] / 128;    // 100000
    int E = in_sizes[1] / 2;      // 1000000
    float* out = (float*)d_out;

    int nb512 = (n + 511) / 512;
    int gemm_blocks = (n + 127) / 128;
    int agg_blocks = (n + 7) / 8;

    // fork: proj GEMM runs concurrently with edge preprocessing
    cudaStream_t s2;
    cudaEvent_t evFork, evJoin;
    bool forked = (cudaStreamCreateWithFlags(&s2, cudaStreamNonBlocking) == cudaSuccess);
    if (forked) {
        cudaEventCreateWithFlags(&evFork, cudaEventDisableTiming);
        cudaEventCreateWithFlags(&evJoin, cudaEventDisableTiming);
        cudaEventRecord(evFork, 0);
        cudaStreamWaitEvent(s2, evFork, 0);
    }
    cudaStream_t sp = forked ? s2 : (cudaStream_t)0;

    k_zero_detect<<<(n + 255) / 256, 256>>>((const unsigned long long*)ei, n);   // stream 0
    k_hist<<<(E + 255) / 256, 256>>>(ei, E);
    k_scan1<<<nb512, 512>>>(n);
    k_tgemm<<<gemm_blocks, 256, 0, sp>>>(x, proj_w, proj_b, /*dst=*/0, n, 128);  // fork branch
    k_scan2<<<1, 256>>>(nb512);
    k_scan3<<<nb512, 512>>>(n);
    k_place<<<(E + 255) / 256, 256>>>(ei, E);

    if (forked) {
        cudaEventRecord(evJoin, s2);
        cudaStreamWaitEvent(0, evJoin, 0);
    }

    for (int l = 0; l < 3; l++) {
        k_tgemm<<<gemm_blocks, 256>>>(nullptr, w[l], nullptr, /*dst=*/1, n, 64);
        float* dst = (l < 2) ? nullptr : out;
        k_agg<<<agg_blocks, 256>>>(b[l], gm[l], bt[l], dst, n, (l < 2) ? 1 : 0);
    }

    if (forked) {
        cudaStreamDestroy(s2);
        cudaEventDestroy(evFork);
        cudaEventDestroy(evJoin);
    }
}

// round 11
// speedup vs baseline: 1.3266x; 1.1468x over previous
#include <cuda_runtime.h>
#include <cuda_bf16.h>
#include <cuda_fp16.h>
#include <cstdint>

#define N_MAX 100352
#define E_MAX 1000000
#define HID 64

// ---------------- device scratch ----------------
__device__ float  g_H  [100000 * HID];   // h / residual (fp32)
__device__ __half g_HWh[100000 * HID];   // dinv[row] * (h @ w)  (fp16, pre-scaled)
__device__ float g_dinv[N_MAX];
__device__ int   g_hist[N_MAX];
__device__ int   g_offs[N_MAX];
__device__ int   g_cur [N_MAX];
__device__ int   g_part[256];
__device__ int   g_esrc[E_MAX];
__device__ int   g_is64;

// ---------------- edge access ----------------
__device__ __forceinline__ int edge_at(const void* ei, int idx) {
    if (g_is64) return (int)((const long long*)ei)[idx];
    return ((const int*)ei)[idx];
}

// ---------------- zero hist + dtype detect (merged) ----------------
__global__ void k_zero_detect(const unsigned long long* __restrict__ ei, int n) {
    int i = blockIdx.x * blockDim.x + threadIdx.x;
    if (i < n) g_hist[i] = 0;
    if (blockIdx.x == 0) {
        int local = 0;
        for (int j = threadIdx.x; j < 1024; j += blockDim.x)
            if ((ei[j] >> 32) != 0ull) local = 1;
        int any = __syncthreads_or(local);
        if (threadIdx.x == 0) g_is64 = (any == 0);
    }
}

__global__ void k_hist(const void* __restrict__ ei, int E) {
    int e = blockIdx.x * blockDim.x + threadIdx.x;
    if (e < E) atomicAdd(&g_hist[edge_at(ei, E + e)], 1);
}

// ---------------- scan1 (+dinv merged) ----------------
__global__ void k_scan1(int n) {
    int idx = blockIdx.x * 512 + threadIdx.x;
    int v = (idx < n) ? g_hist[idx] : 0;
    if (idx < n) g_dinv[idx] = rsqrtf((float)v + 1.0f);
    int lane = threadIdx.x & 31, wid = threadIdx.x >> 5;
    int inc = v;
    #pragma unroll
    for (int o = 1; o < 32; o <<= 1) {
        int t = __shfl_up_sync(0xffffffffu, inc, o);
        if (lane >= o) inc += t;
    }
    __shared__ int wsum[16];
    if (lane == 31) wsum[wid] = inc;
    __syncthreads();
    if (wid == 0) {
        int s = (lane < 16) ? wsum[lane] : 0;
        #pragma unroll
        for (int o = 1; o < 16; o <<= 1) {
            int t = __shfl_up_sync(0xffffffffu, s, o);
            if (lane >= o) s += t;
        }
        if (lane < 16) wsum[lane] = s;
    }
    __syncthreads();
    int base = (wid > 0) ? wsum[wid - 1] : 0;
    if (idx < n) g_offs[idx] = base + inc - v;
    if (threadIdx.x == 0) g_part[blockIdx.x] = wsum[15];
}

__global__ void k_scan2(int nb) {
    int t = threadIdx.x;
    int v = (t < nb) ? g_part[t] : 0;
    int lane = t & 31, wid = t >> 5;
    int inc = v;
    #pragma unroll
    for (int o = 1; o < 32; o <<= 1) {
        int s = __shfl_up_sync(0xffffffffu, inc, o);
        if (lane >= o) inc += s;
    }
    __shared__ int wsum[8];
    if (lane == 31) wsum[wid] = inc;
    __syncthreads();
    if (wid == 0) {
        int s = (lane < 8) ? wsum[lane] : 0;
        #pragma unroll
        for (int o = 1; o < 8; o <<= 1) {
            int u = __shfl_up_sync(0xffffffffu, s, o);
            if (lane >= o) s += u;
        }
        if (lane < 8) wsum[lane] = s;
    }
    __syncthreads();
    int base = (wid > 0) ? wsum[wid - 1] : 0;
    if (t < nb) g_part[t] = base + inc - v;
}

__global__ void k_scan3(int n) {
    int idx = blockIdx.x * 512 + threadIdx.x;
    if (idx < n) {
        int o = g_offs[idx] + g_part[blockIdx.x];
        g_offs[idx] = o;
        g_cur[idx]  = o;
    }
}

__global__ void k_place(const void* __restrict__ ei, int E) {
    int e = blockIdx.x * blockDim.x + threadIdx.x;
    if (e < E) {
        int s = edge_at(ei, e);
        int d = edge_at(ei, E + e);
        int pos = atomicAdd(&g_cur[d], 1);
        g_esrc[pos] = s;
    }
}

// ---------------- bf16 split helpers ----------------
__device__ __forceinline__ unsigned short bits_of(__nv_bfloat16 h) {
    return *(unsigned short*)&h;
}
__device__ __forceinline__ void split2(float x, float y, unsigned& hi, unsigned& lo) {
    __nv_bfloat16 hx = __float2bfloat16_rn(x);
    __nv_bfloat16 hy = __float2bfloat16_rn(y);
    __nv_bfloat16 lx = __float2bfloat16_rn(x - __bfloat162float(hx));
    __nv_bfloat16 ly = __float2bfloat16_rn(y - __bfloat162float(hy));
    hi = (unsigned)bits_of(hx) | ((unsigned)bits_of(hy) << 16);
    lo = (unsigned)bits_of(lx) | ((unsigned)bits_of(ly) << 16);
}

__device__ __forceinline__ void mma16816(float* c, const unsigned* a,
                                         unsigned b0, unsigned b1) {
    asm volatile(
        "mma.sync.aligned.m16n8k16.row.col.f32.bf16.bf16.f32 "
        "{%0,%1,%2,%3}, {%4,%5,%6,%7}, {%8,%9}, {%0,%1,%2,%3};"
        : "+f"(c[0]), "+f"(c[1]), "+f"(c[2]), "+f"(c[3])
        : "r"(a[0]), "r"(a[1]), "r"(a[2]), "r"(a[3]), "r"(b0), "r"(b1));
}

// ---------------- tensor GEMM ----------------
__global__ __launch_bounds__(256) void k_tgemm(
    const float* __restrict__ Aext, const float* __restrict__ W,
    const float* __restrict__ bias, int dst, int n, int K)
{
    const float* A = Aext ? Aext : (const float*)g_H;

    __shared__ __nv_bfloat16 Wh[64][72];
    __shared__ __nv_bfloat16 Wl[64][72];

    int tid = threadIdx.x;
    if (K == 64) {
        #pragma unroll
        for (int u = 0; u < 16; u++) {
            int i = tid * 16 + u;
            int kk = i >> 6, nn = i & 63;
            float wv = W[i];
            __nv_bfloat16 h = __float2bfloat16_rn(wv);
            __nv_bfloat16 l = __float2bfloat16_rn(wv - __bfloat162float(h));
            Wh[nn][kk] = h; Wl[nn][kk] = l;
        }
    }

    int row_base = blockIdx.x * 128;
    int warp = tid >> 5, lane = tid & 31;
    int r = lane >> 2, q = lane & 3;
    int row0 = row_base + warp * 16 + r;
    int rowA0 = min(row0, n - 1);
    int rowA1 = min(row0 + 8, n - 1);

    float c[8][4];
    #pragma unroll
    for (int nf = 0; nf < 8; nf++)
        #pragma unroll
        for (int j = 0; j < 4; j++) c[nf][j] = 0.0f;

    int khalves = K >> 6;
    for (int kh = 0; kh < khalves; kh++) {
        if (K == 128) {
            __syncthreads();
            for (int i = tid; i < 64 * 64; i += 256) {
                int kk = i >> 6, nn = i & 63;
                float wv = W[(kh * 64 + kk) * 64 + nn];
                __nv_bfloat16 h = __float2bfloat16_rn(wv);
                __nv_bfloat16 l = __float2bfloat16_rn(wv - __bfloat162float(h));
                Wh[nn][kk] = h; Wl[nn][kk] = l;
            }
        }
        __syncthreads();

        #pragma unroll
        for (int kc = 0; kc < 4; kc++) {
            int kbase = kh * 64 + kc * 16 + q * 2;
            const float* p0 = A + (size_t)rowA0 * K + kbase;
            const float* p1 = A + (size_t)rowA1 * K + kbase;
            float2 v0 = *(const float2*)p0;
            float2 v1 = *(const float2*)p1;
            float2 v2 = *(const float2*)(p0 + 8);
            float2 v3 = *(const float2*)(p1 + 8);
            unsigned ah[4], al[4];
            split2(v0.x, v0.y, ah[0], al[0]);
            split2(v1.x, v1.y, ah[1], al[1]);
            split2(v2.x, v2.y, ah[2], al[2]);
            split2(v3.x, v3.y, ah[3], al[3]);

            #pragma unroll
            for (int nf = 0; nf < 8; nf++) {
                int bn = nf * 8 + r;
                int bk = kc * 16 + q * 2;
                unsigned bh0 = *(const unsigned*)&Wh[bn][bk];
                unsigned bh1 = *(const unsigned*)&Wh[bn][bk + 8];
                unsigned bl0 = *(const unsigned*)&Wl[bn][bk];
                unsigned bl1 = *(const unsigned*)&Wl[bn][bk + 8];
                mma16816(c[nf], ah, bh0, bh1);
                mma16816(c[nf], al, bh0, bh1);
                mma16816(c[nf], ah, bl0, bl1);
            }
        }
    }

    if (dst == 0) {
        #pragma unroll
        for (int nf = 0; nf < 8; nf++) {
            int col = nf * 8 + q * 2;
            float bx = 0.f, by = 0.f;
            if (bias) { float2 bb = *(const float2*)(bias + col); bx = bb.x; by = bb.y; }
            if (row0 < n)
                *(float2*)(g_H + (size_t)row0 * 64 + col) =
                    make_float2(c[nf][0] + bx, c[nf][1] + by);
            if (row0 + 8 < n)
                *(float2*)(g_H + (size_t)(row0 + 8) * 64 + col) =
                    make_float2(c[nf][2] + bx, c[nf][3] + by);
        }
    } else {
        __half2* Cp = (__half2*)g_HWh;
        float sc0 = (row0 < n) ? g_dinv[row0] : 0.f;
        float sc1 = (row0 + 8 < n) ? g_dinv[row0 + 8] : 0.f;
        #pragma unroll
        for (int nf = 0; nf < 8; nf++) {
            int colh = nf * 4 + q;
            if (row0 < n)
                Cp[(size_t)row0 * 32 + colh] =
                    __floats2half2_rn(c[nf][0] * sc0, c[nf][1] * sc0);
            if (row0 + 8 < n)
                Cp[(size_t)(row0 + 8) * 32 + colh] =
                    __floats2half2_rn(c[nf][2] * sc1, c[nf][3] * sc1);
        }
    }
}

// ---------------- fused aggregate + bias + LN (+ReLU+residual) ----------
// 4 nodes / warp, 8 lanes per node, lane covers 8 fp16 cols via uint4 LDG.128
__global__ __launch_bounds__(256) void k_agg(
    const float* __restrict__ bias, const float* __restrict__ gma,
    const float* __restrict__ beta, float* __restrict__ out_ext,
    int n, int relu_res)
{
    int warp = (blockIdx.x * blockDim.x + threadIdx.x) >> 5;
    int lane = threadIdx.x & 31;
    int grp = lane >> 3, sub = lane & 7;
    int node = warp * 4 + grp;
    bool valid = (node < n);
    int nodeL = valid ? node : (n - 1);

    float* out = out_ext ? out_ext : (float*)g_H;
    const uint4* HW4 = (const uint4*)g_HWh;     // 8 uint4 per row

    // self term
    uint4 sv = HW4[(size_t)nodeL * 8 + sub];
    float2 aA[4], aB[4];
    #pragma unroll
    for (int i = 0; i < 4; i++) {
        aA[i] = __half22float2(((const __half2*)&sv)[i]);
        aB[i] = make_float2(0.f, 0.f);
    }

    int e = valid ? g_offs[nodeL] : 0;
    int e_end = valid ? (e + g_hist[nodeL]) : 0;
    for (; e + 2 <= e_end; e += 2) {
        int s0 = g_esrc[e];
        int s1 = g_esrc[e + 1];
        uint4 u0 = HW4[(size_t)s0 * 8 + sub];
        uint4 u1 = HW4[(size_t)s1 * 8 + sub];
        #pragma unroll
        for (int i = 0; i < 4; i++) {
            float2 f0 = __half22float2(((const __half2*)&u0)[i]);
            float2 f1 = __half22float2(((const __half2*)&u1)[i]);
            aA[i].x += f0.x; aA[i].y += f0.y;
            aB[i].x += f1.x; aB[i].y += f1.y;
        }
    }
    if (e < e_end) {
        int s0 = g_esrc[e];
        uint4 u0 = HW4[(size_t)s0 * 8 + sub];
        #pragma unroll
        for (int i = 0; i < 4; i++) {
            float2 f0 = __half22float2(((const __half2*)&u0)[i]);
            aA[i].x += f0.x; aA[i].y += f0.y;
        }
    }

    float di = g_dinv[nodeL];
    float v[8];
    #pragma unroll
    for (int i = 0; i < 4; i++) {
        v[2 * i]     = (aA[i].x + aB[i].x) * di;
        v[2 * i + 1] = (aA[i].y + aB[i].y) * di;
    }

    // + bias
    float4 b0 = ((const float4*)bias)[sub * 2];
    float4 b1 = ((const float4*)bias)[sub * 2 + 1];
    v[0] += b0.x; v[1] += b0.y; v[2] += b0.z; v[3] += b0.w;
    v[4] += b1.x; v[5] += b1.y; v[6] += b1.z; v[7] += b1.w;

    // LayerNorm over 64 cols: local 8 + group-of-8 shfl reduction
    float sum = ((v[0] + v[1]) + (v[2] + v[3])) + ((v[4] + v[5]) + (v[6] + v[7]));
    #pragma unroll
    for (int o = 4; o; o >>= 1) sum += __shfl_xor_sync(0xffffffffu, sum, o);
    float mu = sum * (1.0f / 64.0f);
    float vs = 0.f;
    #pragma unroll
    for (int i = 0; i < 8; i++) { v[i] -= mu; vs += v[i] * v[i]; }
    #pragma unroll
    for (int o = 4; o; o >>= 1) vs += __shfl_xor_sync(0xffffffffu, vs, o);
    float rstd = rsqrtf(vs * (1.0f / 64.0f) + 1e-5f);

    float4 g0 = ((const float4*)gma)[sub * 2];
    float4 g1 = ((const float4*)gma)[sub * 2 + 1];
    float4 t0 = ((const float4*)beta)[sub * 2];
    float4 t1 = ((const float4*)beta)[sub * 2 + 1];
    float o0x = v[0] * rstd * g0.x + t0.x, o0y = v[1] * rstd * g0.y + t0.y;
    float o0z = v[2] * rstd * g0.z + t0.z, o0w = v[3] * rstd * g0.w + t0.w;
    float o1x = v[4] * rstd * g1.x + t1.x, o1y = v[5] * rstd * g1.y + t1.y;
    float o1z = v[6] * rstd * g1.z + t1.z, o1w = v[7] * rstd * g1.w + t1.w;

    if (!valid) return;

    if (relu_res) {
        float4* Hrow = (float4*)(g_H + (size_t)node * 64) + sub * 2;
        float4 r0 = Hrow[0], r1 = Hrow[1];
        o0x = fmaxf(o0x, 0.f) + r0.x; o0y = fmaxf(o0y, 0.f) + r0.y;
        o0z = fmaxf(o0z, 0.f) + r0.z; o0w = fmaxf(o0w, 0.f) + r0.w;
        o1x = fmaxf(o1x, 0.f) + r1.x; o1y = fmaxf(o1y, 0.f) + r1.y;
        o1z = fmaxf(o1z, 0.f) + r1.z; o1w = fmaxf(o1w, 0.f) + r1.w;
        Hrow[0] = make_float4(o0x, o0y, o0z, o0w);
        Hrow[1] = make_float4(o1x, o1y, o1z, o1w);
    } else {
        float4* Orow = (float4*)(out + (size_t)node * 64) + sub * 2;
        Orow[0] = make_float4(o0x, o0y, o0z, o0w);
        Orow[1] = make_float4(o1x, o1y, o1z, o1w);
    }
}

// ---------------- launch ----------------
extern "C" void kernel_launch(void* const* d_in, const int* in_sizes, int n_in,
                              void* d_out, int out_size)
{
    const float* x      = (const float*)d_in[0];
    const void*  ei     = d_in[1];
    const float* proj_w = (const float*)d_in[2];
    const float* proj_b = (const float*)d_in[3];
    const float* w[3]  = { (const float*)d_in[4],  (const float*)d_in[8],  (const float*)d_in[12] };
    const float* b[3]  = { (const float*)d_in[5],  (const float*)d_in[9],  (const float*)d_in[13] };
    const float* gm[3] = { (const float*)d_in[6],  (const float*)d_in[10], (const float*)d_in[14] };
    const float* bt[3] = { (const float*)d_in[7],  (const float*)d_in[11], (const float*)d_in[15] };

    int n = in_sizes[0] / 128;    // 100000
    int E = in_sizes[1] / 2;      // 1000000
    float* out = (float*)d_out;

    int nb512 = (n + 511) / 512;
    int gemm_blocks = (n + 127) / 128;
    int agg_blocks = (n + 31) / 32;     // 4 nodes per warp, 8 warps per block

    cudaStream_t s2;
    cudaEvent_t evFork, evScan1, evJoin;
    bool forked = (cudaStreamCreateWithFlags(&s2, cudaStreamNonBlocking) == cudaSuccess);
    if (forked) {
        cudaEventCreateWithFlags(&evFork,  cudaEventDisableTiming);
        cudaEventCreateWithFlags(&evScan1, cudaEventDisableTiming);
        cudaEventCreateWithFlags(&evJoin,  cudaEventDisableTiming);
        cudaEventRecord(evFork, 0);
        cudaStreamWaitEvent(s2, evFork, 0);
    }
    cudaStream_t sp = forked ? s2 : (cudaStream_t)0;

    k_zero_detect<<<(n + 255) / 256, 256>>>((const unsigned long long*)ei, n);
    k_hist<<<(E + 255) / 256, 256>>>(ei, E);
    k_scan1<<<nb512, 512>>>(n);                         // produces g_dinv
    if (forked) cudaEventRecord(evScan1, 0);

    // fork branch: proj GEMM, then layer-1 GEMM (needs g_H + g_dinv, not edges)
    k_tgemm<<<gemm_blocks, 256, 0, sp>>>(x, proj_w, proj_b, /*dst=*/0, n, 128);
    if (forked) cudaStreamWaitEvent(s2, evScan1, 0);
    k_tgemm<<<gemm_blocks, 256, 0, sp>>>(nullptr, w[0], nullptr, /*dst=*/1, n, 64);

    k_scan2<<<1, 256>>>(nb512);
    k_scan3<<<nb512, 512>>>(n);
    k_place<<<(E + 255) / 256, 256>>>(ei, E);

    if (forked) {
        cudaEventRecord(evJoin, s2);
        cudaStreamWaitEvent(0, evJoin, 0);
    } else {
        // without fork, gemm for layer 0 must run here (it ran inline above on stream 0)
    }

    for (int l = 0; l < 3; l++) {
        if (l > 0)
            k_tgemm<<<gemm_blocks, 256>>>(nullptr, w[l], nullptr, /*dst=*/1, n, 64);
        float* dst = (l < 2) ? nullptr : out;
        k_agg<<<agg_blocks, 256>>>(b[l], gm[l], bt[l], dst, n, (l < 2) ? 1 : 0);
    }

    if (forked) {
        cudaStreamDestroy(s2);
        cudaEventDestroy(evFork);
        cudaEventDestroy(evScan1);
        cudaEventDestroy(evJoin);
    }
}